// round 5
// baseline (speedup 1.0000x reference)
#include <cuda_runtime.h>
#include <cuda_bf16.h>

#define N_NODES 50000
#define N_EDGES 800000
#define NODE_DIM 64
#define HIDDEN 128
#define OUT_DIM 256
#define N_LAYERS 3
#define SCAN_BLOCKS ((N_NODES + 255) / 256)   // 196

typedef unsigned long long u64;

// Scratch (static device globals; no runtime allocation)
__device__ float d_hbuf0[(size_t)N_NODES * HIDDEN];
__device__ float d_hbuf1[(size_t)N_NODES * HIDDEN];
__device__ __nv_bfloat16 d_hb0[(size_t)N_NODES * HIDDEN];  // bf16 shadow of hbuf0
__device__ __nv_bfloat16 d_hb1[(size_t)N_NODES * HIDDEN];  // bf16 shadow of hbuf1
__device__ float d_deg[N_NODES];      // 1/deg (0 for isolated nodes)
__device__ float d_gsum[HIDDEN];
__device__ int   d_cnt[N_NODES];      // histogram
__device__ int   d_row[N_NODES + 1];  // CSR row offsets
__device__ int   d_cur[N_NODES];      // fill cursors
__device__ int   d_colA[N_EDGES];     // CSR column (src node per edge slot)
__device__ int   d_bsum[SCAN_BLOCKS];

// ---- packed f32x2 helpers (Blackwell dual-FMA) -----------------------------
__device__ __forceinline__ u64 pack2(float lo, float hi) {
    u64 r;
    asm("mov.b64 %0, {%1, %2};" : "=l"(r)
        : "r"(__float_as_uint(lo)), "r"(__float_as_uint(hi)));
    return r;
}
__device__ __forceinline__ void unpack2(u64 v, float& lo, float& hi) {
    unsigned int a, b;
    asm("mov.b64 {%0, %1}, %2;" : "=r"(a), "=r"(b) : "l"(v));
    lo = __uint_as_float(a);
    hi = __uint_as_float(b);
}
__device__ __forceinline__ void fma2(u64& acc, u64 a, u64 b) {
    asm("fma.rn.f32x2 %0, %1, %2, %0;" : "+l"(acc) : "l"(a), "l"(b));
}

// bf16x4 (uint2) -> accumulate into float4
__device__ __forceinline__ void acc_bf16(float4& a, uint2 v) {
    __nv_bfloat162 b0 = *reinterpret_cast<const __nv_bfloat162*>(&v.x);
    __nv_bfloat162 b1 = *reinterpret_cast<const __nv_bfloat162*>(&v.y);
    float2 f0 = __bfloat1622float2(b0);
    float2 f1 = __bfloat1622float2(b1);
    a.x += f0.x; a.y += f0.y; a.z += f1.x; a.w += f1.y;
}

// float4 -> bf16x4 (uint2)
__device__ __forceinline__ uint2 to_bf16x4(float4 r) {
    __nv_bfloat162 b0 = __float22bfloat162_rn(make_float2(r.x, r.y));
    __nv_bfloat162 b1 = __float22bfloat162_rn(make_float2(r.z, r.w));
    uint2 o;
    o.x = *reinterpret_cast<const unsigned int*>(&b0);
    o.y = *reinterpret_cast<const unsigned int*>(&b1);
    return o;
}

// ---------------------------------------------------------------------------
__global__ void init_kernel() {
    int i = blockIdx.x * blockDim.x + threadIdx.x;
    if (i < N_NODES) d_cnt[i] = 0;
    if (i < HIDDEN) d_gsum[i] = 0.0f;
}

__global__ void hist_kernel(const int* __restrict__ dst) {
    int e = blockIdx.x * blockDim.x + threadIdx.x;
    if (e < N_EDGES) atomicAdd(&d_cnt[dst[e]], 1);
}

__global__ void scan1_kernel() {
    __shared__ int sd[256];
    int t = threadIdx.x;
    int i = blockIdx.x * 256 + t;
    int v = (i < N_NODES) ? d_cnt[i] : 0;
    sd[t] = v;
    __syncthreads();
#pragma unroll
    for (int off = 1; off < 256; off <<= 1) {
        int a = (t >= off) ? sd[t - off] : 0;
        __syncthreads();
        sd[t] += a;
        __syncthreads();
    }
    if (i < N_NODES) d_row[i] = sd[t] - v;   // exclusive
    if (t == 255) d_bsum[blockIdx.x] = sd[t];
}

__global__ void scan2_kernel() {
    __shared__ int sd[256];
    int t = threadIdx.x;
    int v = (t < SCAN_BLOCKS) ? d_bsum[t] : 0;
    sd[t] = v;
    __syncthreads();
#pragma unroll
    for (int off = 1; off < 256; off <<= 1) {
        int a = (t >= off) ? sd[t - off] : 0;
        __syncthreads();
        sd[t] += a;
        __syncthreads();
    }
    if (t < SCAN_BLOCKS) d_bsum[t] = sd[t] - v;  // exclusive
}

__global__ void scan3_kernel() {
    int i = blockIdx.x * blockDim.x + threadIdx.x;
    if (i < N_NODES) {
        int r = d_row[i] + d_bsum[blockIdx.x];
        d_row[i] = r;
        d_cur[i] = r;
        int c = d_cnt[i];
        d_deg[i] = (c > 0) ? (1.0f / (float)c) : 0.0f;
    }
    if (i == 0) d_row[N_NODES] = N_EDGES;
}

__global__ void fill_kernel(const int* __restrict__ src, const int* __restrict__ dst) {
    int e = blockIdx.x * blockDim.x + threadIdx.x;
    if (e < N_EDGES) {
        int d = dst[e];
        int pos = atomicAdd(&d_cur[d], 1);
        d_colA[pos] = src[e];
    }
}

// ---------------------------------------------------------------------------
// h0 = x @ Wp + bp   (x: [N,64], Wp: [64,128]) -> d_hbuf0 (+ bf16 shadow)
// 128 threads, 32 nodes; thread (nt,ct) owns 8 nodes x 4 cols.
__global__ void __launch_bounds__(128) proj_kernel(const float* __restrict__ x,
                            const float* __restrict__ Wp,
                            const float* __restrict__ bp) {
    __shared__ float xs[32][NODE_DIM];
    int t = threadIdx.x;
    int node0 = blockIdx.x * 32;

    for (int i = t; i < 32 * (NODE_DIM / 4); i += 128) {
        int r = i >> 4;
        int c4 = i & 15;
        int node = node0 + r;
        float4 v = make_float4(0.f, 0.f, 0.f, 0.f);
        if (node < N_NODES)
            v = ((const float4*)(x + (size_t)node * NODE_DIM))[c4];
        *(float4*)&xs[r][c4 * 4] = v;
    }
    __syncthreads();

    int ct = t & 31;
    int nt = t >> 5;
    int colb = ct * 4;

    u64 acc2[8][2];
#pragma unroll
    for (int i = 0; i < 8; i++) { acc2[i][0] = 0ull; acc2[i][1] = 0ull; }

    const float4* W4 = (const float4*)Wp;
#pragma unroll 4
    for (int k = 0; k < NODE_DIM; k++) {
        float4 w = W4[k * 32 + ct];
        u64 wp0 = pack2(w.x, w.y);
        u64 wp1 = pack2(w.z, w.w);
#pragma unroll
        for (int i = 0; i < 8; i++) {
            float m = xs[nt * 8 + i][k];
            u64 mp = pack2(m, m);
            fma2(acc2[i][0], mp, wp0);
            fma2(acc2[i][1], mp, wp1);
        }
    }

    float4 bv = ((const float4*)bp)[ct];
#pragma unroll
    for (int i = 0; i < 8; i++) {
        int node = node0 + nt * 8 + i;
        if (node < N_NODES) {
            float4 r;
            unpack2(acc2[i][0], r.x, r.y);
            unpack2(acc2[i][1], r.z, r.w);
            r.x += bv.x; r.y += bv.y; r.z += bv.z; r.w += bv.w;
            *(float4*)(d_hbuf0 + (size_t)node * HIDDEN + colb) = r;
            *(uint2*)(d_hb0 + (size_t)node * HIDDEN + colb) = to_bf16x4(r);
        }
    }
}

// ---------------------------------------------------------------------------
// Fused GNN layer: hout = relu(hin + (gather_mean(hbin) @ Wg) + bg)
// Gather reads the bf16 shadow (256 B/row -> half the L2 traffic/wavefronts);
// residual + GEMM stay fp32. Warp w owns nodes w*8..+7, two nodes' edge lists
// interleaved, unroll-4 each (8 LDG.64 in flight per lane).
__global__ void __launch_bounds__(128) layer_kernel(const float* __restrict__ hin,
                             const __nv_bfloat16* __restrict__ hbin,
                             float* __restrict__ hout,
                             __nv_bfloat16* __restrict__ hbout,
                             const float* __restrict__ Wg,
                             const float* __restrict__ bg) {
    __shared__ float ms[32][HIDDEN];
    int t = threadIdx.x;
    int node0 = blockIdx.x * 32;
    int lane = t & 31;
    int w = t >> 5;   // warp 0..3

#pragma unroll 1
    for (int ii = 0; ii < 8; ii += 2) {
        int nlA = w * 8 + ii;
        int nlB = nlA + 1;
        int nA = node0 + nlA;
        int nB = node0 + nlB;

        float4 aA = make_float4(0.f, 0.f, 0.f, 0.f);
        float4 aB = aA;

        int jA = 0, eA = 0, jB = 0, eB = 0;
        float invA = 0.0f, invB = 0.0f;
        if (nA < N_NODES) { jA = d_row[nA]; eA = d_row[nA + 1]; invA = d_deg[nA]; }
        if (nB < N_NODES) { jB = d_row[nB]; eB = d_row[nB + 1]; invB = d_deg[nB]; }

        // Joint loop: 4 edges from A + 4 edges from B per iteration.
#pragma unroll 1
        while (jA + 4 <= eA && jB + 4 <= eB) {
            int sA0 = d_colA[jA],     sA1 = d_colA[jA + 1];
            int sA2 = d_colA[jA + 2], sA3 = d_colA[jA + 3];
            int sB0 = d_colA[jB],     sB1 = d_colA[jB + 1];
            int sB2 = d_colA[jB + 2], sB3 = d_colA[jB + 3];
            uint2 vA0 = ((const uint2*)(hbin + (size_t)sA0 * HIDDEN))[lane];
            uint2 vA1 = ((const uint2*)(hbin + (size_t)sA1 * HIDDEN))[lane];
            uint2 vA2 = ((const uint2*)(hbin + (size_t)sA2 * HIDDEN))[lane];
            uint2 vA3 = ((const uint2*)(hbin + (size_t)sA3 * HIDDEN))[lane];
            uint2 vB0 = ((const uint2*)(hbin + (size_t)sB0 * HIDDEN))[lane];
            uint2 vB1 = ((const uint2*)(hbin + (size_t)sB1 * HIDDEN))[lane];
            uint2 vB2 = ((const uint2*)(hbin + (size_t)sB2 * HIDDEN))[lane];
            uint2 vB3 = ((const uint2*)(hbin + (size_t)sB3 * HIDDEN))[lane];
            acc_bf16(aA, vA0); acc_bf16(aA, vA1);
            acc_bf16(aA, vA2); acc_bf16(aA, vA3);
            acc_bf16(aB, vB0); acc_bf16(aB, vB1);
            acc_bf16(aB, vB2); acc_bf16(aB, vB3);
            jA += 4; jB += 4;
        }
        // Drain A
#pragma unroll 1
        while (jA + 4 <= eA) {
            int s0 = d_colA[jA],     s1 = d_colA[jA + 1];
            int s2 = d_colA[jA + 2], s3 = d_colA[jA + 3];
            uint2 v0 = ((const uint2*)(hbin + (size_t)s0 * HIDDEN))[lane];
            uint2 v1 = ((const uint2*)(hbin + (size_t)s1 * HIDDEN))[lane];
            uint2 v2 = ((const uint2*)(hbin + (size_t)s2 * HIDDEN))[lane];
            uint2 v3 = ((const uint2*)(hbin + (size_t)s3 * HIDDEN))[lane];
            acc_bf16(aA, v0); acc_bf16(aA, v1);
            acc_bf16(aA, v2); acc_bf16(aA, v3);
            jA += 4;
        }
#pragma unroll 1
        while (jA < eA) {
            int s = d_colA[jA++];
            uint2 v = ((const uint2*)(hbin + (size_t)s * HIDDEN))[lane];
            acc_bf16(aA, v);
        }
        // Drain B
#pragma unroll 1
        while (jB + 4 <= eB) {
            int s0 = d_colA[jB],     s1 = d_colA[jB + 1];
            int s2 = d_colA[jB + 2], s3 = d_colA[jB + 3];
            uint2 v0 = ((const uint2*)(hbin + (size_t)s0 * HIDDEN))[lane];
            uint2 v1 = ((const uint2*)(hbin + (size_t)s1 * HIDDEN))[lane];
            uint2 v2 = ((const uint2*)(hbin + (size_t)s2 * HIDDEN))[lane];
            uint2 v3 = ((const uint2*)(hbin + (size_t)s3 * HIDDEN))[lane];
            acc_bf16(aB, v0); acc_bf16(aB, v1);
            acc_bf16(aB, v2); acc_bf16(aB, v3);
            jB += 4;
        }
#pragma unroll 1
        while (jB < eB) {
            int s = d_colA[jB++];
            uint2 v = ((const uint2*)(hbin + (size_t)s * HIDDEN))[lane];
            acc_bf16(aB, v);
        }

        float4 rA, rB;
        rA.x = aA.x * invA; rA.y = aA.y * invA;
        rA.z = aA.z * invA; rA.w = aA.w * invA;
        rB.x = aB.x * invB; rB.y = aB.y * invB;
        rB.z = aB.z * invB; rB.w = aB.w * invB;
        *(float4*)&ms[nlA][lane * 4] = rA;
        *(float4*)&ms[nlB][lane * 4] = rB;
    }
    __syncthreads();

    // Phase 2: (ms @ Wg) — thread (nt=w, ct=lane) owns 8 nodes x 4 cols
    int ct = lane;
    int nt = w;
    int colb = ct * 4;

    u64 acc2[8][2];
#pragma unroll
    for (int i = 0; i < 8; i++) { acc2[i][0] = 0ull; acc2[i][1] = 0ull; }

    const float4* W4 = (const float4*)Wg;
#pragma unroll 4
    for (int k = 0; k < HIDDEN; k++) {
        float4 wv = W4[k * 32 + ct];
        u64 wp0 = pack2(wv.x, wv.y);
        u64 wp1 = pack2(wv.z, wv.w);
#pragma unroll
        for (int i = 0; i < 8; i++) {
            float m = ms[nt * 8 + i][k];
            u64 mp = pack2(m, m);
            fma2(acc2[i][0], mp, wp0);
            fma2(acc2[i][1], mp, wp1);
        }
    }

    float4 bv = ((const float4*)bg)[ct];
#pragma unroll
    for (int i = 0; i < 8; i++) {
        int node = node0 + nt * 8 + i;
        if (node < N_NODES) {
            float4 hv = *(const float4*)(hin + (size_t)node * HIDDEN + colb);
            float lo, hi;
            float4 r;
            unpack2(acc2[i][0], lo, hi);
            r.x = fmaxf(hv.x + lo + bv.x, 0.0f);
            r.y = fmaxf(hv.y + hi + bv.y, 0.0f);
            unpack2(acc2[i][1], lo, hi);
            r.z = fmaxf(hv.z + lo + bv.z, 0.0f);
            r.w = fmaxf(hv.w + hi + bv.w, 0.0f);
            *(float4*)(hout + (size_t)node * HIDDEN + colb) = r;
            *(uint2*)(hbout + (size_t)node * HIDDEN + colb) = to_bf16x4(r);
        }
    }
}

// ---------------------------------------------------------------------------
__global__ void reduce_kernel(const float* __restrict__ h) {
    int t = threadIdx.x;   // 256
    int col = t & 127;
    int rh = t >> 7;
    float acc = 0.0f;
    for (int node = blockIdx.x * 2 + rh; node < N_NODES; node += gridDim.x * 2)
        acc += h[(size_t)node * HIDDEN + col];
    atomicAdd(&d_gsum[col], acc);
}

__global__ void mlp_kernel(const float* __restrict__ W1,
                           const float* __restrict__ b1,
                           const float* __restrict__ W2,
                           const float* __restrict__ b2,
                           float* __restrict__ out) {
    __shared__ float gs[HIDDEN];
    __shared__ float ts[HIDDEN];
    int t = threadIdx.x;  // 256
    if (t < HIDDEN) gs[t] = d_gsum[t] * (1.0f / (float)N_NODES);
    __syncthreads();
    if (t < HIDDEN) {
        float a = b1[t];
#pragma unroll 8
        for (int k = 0; k < HIDDEN; k++) a += gs[k] * W1[k * HIDDEN + t];
        ts[t] = fmaxf(a, 0.0f);
    }
    __syncthreads();
    {
        float a = b2[t];
#pragma unroll 8
        for (int k = 0; k < HIDDEN; k++) a += ts[k] * W2[k * OUT_DIM + t];
        out[t] = a;
    }
}

// ---------------------------------------------------------------------------
extern "C" void kernel_launch(void* const* d_in, const int* in_sizes, int n_in,
                              void* d_out, int out_size) {
    const float* x   = (const float*)d_in[0];
    const int*   src = (const int*)d_in[1];
    const int*   dst = (const int*)d_in[2];
    const float* Wp  = (const float*)d_in[3];
    const float* bp  = (const float*)d_in[4];
    const float* Wg  = (const float*)d_in[5];
    const float* bg  = (const float*)d_in[6];
    const float* W1  = (const float*)d_in[7];
    const float* b1  = (const float*)d_in[8];
    const float* W2  = (const float*)d_in[9];
    const float* b2  = (const float*)d_in[10];
    float* out = (float*)d_out;

    float *h0, *h1;
    __nv_bfloat16 *hb0, *hb1;
    cudaGetSymbolAddress((void**)&h0, d_hbuf0);
    cudaGetSymbolAddress((void**)&h1, d_hbuf1);
    cudaGetSymbolAddress((void**)&hb0, d_hb0);
    cudaGetSymbolAddress((void**)&hb1, d_hb1);

    // CSR build
    init_kernel<<<(N_NODES + 255) / 256, 256>>>();
    hist_kernel<<<(N_EDGES + 255) / 256, 256>>>(dst);
    scan1_kernel<<<SCAN_BLOCKS, 256>>>();
    scan2_kernel<<<1, 256>>>();
    scan3_kernel<<<SCAN_BLOCKS, 256>>>();
    fill_kernel<<<(N_EDGES + 255) / 256, 256>>>(src, dst);

    // node projection
    proj_kernel<<<(N_NODES + 31) / 32, 128>>>(x, Wp, bp);

    // GNN layers with ping-pong buffers
    const int nblocks = (N_NODES + 31) / 32;
    float* bufs[2] = {h0, h1};
    __nv_bfloat16* bbufs[2] = {hb0, hb1};
    for (int l = 0; l < N_LAYERS; l++) {
        float* hin  = bufs[l & 1];
        float* hout = bufs[(l + 1) & 1];
        layer_kernel<<<nblocks, 128>>>(hin, bbufs[l & 1], hout, bbufs[(l + 1) & 1],
                                       Wg + (size_t)l * HIDDEN * HIDDEN,
                                       bg + (size_t)l * HIDDEN);
    }

    // mean over nodes + MLP head
    reduce_kernel<<<256, 256>>>(bufs[N_LAYERS & 1]);
    mlp_kernel<<<1, 256>>>(W1, b1, W2, b2, out);
}